// round 6
// baseline (speedup 1.0000x reference)
#include <cuda_runtime.h>
#include <math.h>

// Problem constants
#define Bq 2
#define Sq 2048
#define DM 1024
#define Hq 16
#define DHq 64

// ---------------------------------------------------------------------------
// Scratch (__device__ globals; no runtime allocation)
// ---------------------------------------------------------------------------
__device__ float g_qh [(size_t)Bq * Hq * Sq * DHq];   // [B,H,S,DH]
__device__ float g_kh [(size_t)Bq * Hq * Sq * DHq];   // [B,H,S,DH]
__device__ float g_vh [(size_t)Bq * Hq * Sq * DHq];   // [B,H,S,DH]
__device__ float g_ctx[(size_t)Bq * Sq * DM];          // [B,S,DM]

// ---------------------------------------------------------------------------
// Helpers
// ---------------------------------------------------------------------------
__device__ __forceinline__ unsigned f2tf32(float f) {
    unsigned r; asm("cvt.rna.tf32.f32 %0, %1;" : "=r"(r) : "f"(f)); return r;
}
__device__ __forceinline__ void cpa16(void* dst, const void* src) {
    unsigned d = (unsigned)__cvta_generic_to_shared(dst);
    asm volatile("cp.async.cg.shared.global [%0], [%1], 16;" :: "r"(d), "l"(src));
}
__device__ __forceinline__ void cp_commit() { asm volatile("cp.async.commit_group;"); }
__device__ __forceinline__ void cp_wait1()  { asm volatile("cp.async.wait_group 1;"); }

__device__ __forceinline__ void mma8(float* c, unsigned a0, unsigned a1, unsigned a2,
                                     unsigned a3, unsigned b0, unsigned b1) {
    asm volatile(
        "mma.sync.aligned.m16n8k8.row.col.f32.tf32.tf32.f32 "
        "{%0,%1,%2,%3}, {%4,%5,%6,%7}, {%8,%9}, {%0,%1,%2,%3};"
        : "+f"(c[0]), "+f"(c[1]), "+f"(c[2]), "+f"(c[3])
        : "r"(a0), "r"(a1), "r"(a2), "r"(a3), "r"(b0), "r"(b1));
}

// convert a float4 slot in smem to tf32 bits in place
__device__ __forceinline__ void cvt4_inplace(float* p) {
    float4 v = *(float4*)p;
    uint4 u = make_uint4(f2tf32(v.x), f2tf32(v.y), f2tf32(v.z), f2tf32(v.w));
    *(uint4*)p = u;
}

// ---------------------------------------------------------------------------
// Projection GEMM: Y = X @ W^T + bias  (tiles converted to tf32 in smem once)
// ---------------------------------------------------------------------------
struct GemmP {
    const float *X, *W, *bias; float *Y;
    const float *X1, *W1, *b1; float *Y1;
    const float *X2, *W2, *b2; float *Y2;
    int M, N, K;
    int out_mode;   // 0: Y[m*N+n] ; 1: head layout ((b*H+h)*S+s)*DH+d
    int qkv;
};

#define AS   36
#define A_WORDS 4608     // 128*36
#define G_SMEM_BYTES (4 * A_WORDS * 4)

__global__ __launch_bounds__(256)
void gemm_tc(GemmP p)
{
    const int m0 = blockIdx.y * 128;
    const int n0 = blockIdx.x * 128;
    const int z  = blockIdx.z;
    const int tid = threadIdx.x, lane = tid & 31, warp = tid >> 5;
    const int wm = warp & 1, wn = warp >> 1;

    const float *X = p.X, *W = p.W, *bias = p.bias; float* Y = p.Y;
    if (p.qkv) {
        if (z == 1) { X = p.X1; W = p.W1; bias = p.b1; Y = p.Y1; }
        else if (z == 2) { X = p.X2; W = p.W2; bias = p.b2; Y = p.Y2; }
    }

    extern __shared__ float sm[];
    float* Abuf[2] = { sm,               sm + A_WORDS     };
    float* Bbuf[2] = { sm + 2 * A_WORDS, sm + 3 * A_WORDS };

    auto loadA = [&](float* As_, int k0) {
        int r0 = tid >> 3, c = (tid & 7) * 4;
#pragma unroll
        for (int it = 0; it < 4; it++) {
            int r = r0 + it * 32;
            cpa16(&As_[r * AS + c], &X[(long long)(m0 + r) * p.K + k0 + c]);
        }
    };
    auto loadB = [&](float* Bs_, int k0) {
        int r0 = tid >> 3, c = (tid & 7) * 4;
#pragma unroll
        for (int it = 0; it < 4; it++) {
            int r = r0 + it * 32;
            cpa16(&Bs_[r * AS + c], &W[(long long)(n0 + r) * p.K + k0 + c]);
        }
    };

    float acc[4][4][4] = {};

    loadA(Abuf[0], 0); loadB(Bbuf[0], 0); cp_commit();
    int st = 0;
    for (int k0 = 0; k0 < p.K; k0 += 32) {
        if (k0 + 32 < p.K) { loadA(Abuf[st ^ 1], k0 + 32); loadB(Bbuf[st ^ 1], k0 + 32); }
        cp_commit();
        cp_wait1();
        __syncthreads();

        // convert arrived tiles to tf32 bits in place (once)
        {
            float* As_ = Abuf[st];
            float* Bs_ = Bbuf[st];
#pragma unroll
            for (int it = 0; it < 4; it++) {
                int i = tid + it * 256;
                int r = i >> 3, c4 = (i & 7) * 4;
                cvt4_inplace(&As_[r * AS + c4]);
                cvt4_inplace(&Bs_[r * AS + c4]);
            }
        }
        __syncthreads();

        const unsigned* As_ = (const unsigned*)Abuf[st];
        const unsigned* Bs_ = (const unsigned*)Bbuf[st];
#pragma unroll
        for (int kk = 0; kk < 32; kk += 8) {
            unsigned a[4][4];
#pragma unroll
            for (int i = 0; i < 4; i++) {
                int mr = wm * 64 + i * 16 + (lane >> 2);
                int kc = kk + (lane & 3);
                a[i][0] = As_[mr * AS + kc];
                a[i][1] = As_[(mr + 8) * AS + kc];
                a[i][2] = As_[mr * AS + kc + 4];
                a[i][3] = As_[(mr + 8) * AS + kc + 4];
            }
            unsigned b[4][2];
#pragma unroll
            for (int j = 0; j < 4; j++) {
                int nr = wn * 32 + j * 8 + (lane >> 2);
                int kc = kk + (lane & 3);
                b[j][0] = Bs_[nr * AS + kc];
                b[j][1] = Bs_[nr * AS + kc + 4];
            }
#pragma unroll
            for (int i = 0; i < 4; i++)
#pragma unroll
                for (int j = 0; j < 4; j++)
                    mma8(acc[i][j], a[i][0], a[i][1], a[i][2], a[i][3], b[j][0], b[j][1]);
        }
        __syncthreads();
        st ^= 1;
    }

#pragma unroll
    for (int i = 0; i < 4; i++)
#pragma unroll
        for (int j = 0; j < 4; j++)
#pragma unroll
            for (int h = 0; h < 2; h++) {
                int m = m0 + wm * 64 + i * 16 + (lane >> 2) + h * 8;
                int n = n0 + wn * 32 + j * 8 + (lane & 3) * 2;
                float v0 = acc[i][j][h * 2]     + (bias ? bias[n]     : 0.f);
                float v1 = acc[i][j][h * 2 + 1] + (bias ? bias[n + 1] : 0.f);
                long long idx;
                if (p.out_mode == 0) {
                    idx = (long long)m * p.N + n;
                } else {
                    int b_ = m >> 11;
                    int s  = m & (Sq - 1);
                    int hh = n >> 6;
                    int d  = n & (DHq - 1);
                    idx = (((long long)b_ * Hq + hh) * Sq + s) * DHq + d;
                }
                *(float2*)&Y[idx] = make_float2(v0, v1);
            }
}

// ---------------------------------------------------------------------------
// Fused flash attention. 512 threads = 16 warps.
// Warp pair (slab = warp>>1) shares 16 Q rows; jh = warp&1 owns a 64-column
// half of S and the matching k-half of P@V. Partial ctx/l merged via smem.
// K/V tiles converted to tf32 in smem once per arrival.
// qt is reversed so the longest causal blocks launch first.
// ---------------------------------------------------------------------------
#define QS_OFF 0
#define KS_OFF 8704            // Qs: 128*68
#define VS_OFF (8704 + 2*8704) // Ks: 2 x 128*68
#define F_SMEM_WORDS (26112 + 2*9216)
#define F_SMEM_BYTES (F_SMEM_WORDS * 4)

__global__ __launch_bounds__(512, 1)
void attn_flash(const float* __restrict__ qh, const float* __restrict__ kh,
                const float* __restrict__ vh, float* __restrict__ ctx,
                float* __restrict__ attn, int write_attn)
{
    const int qt = (int)gridDim.x - 1 - (int)blockIdx.x;  // long blocks first
    const int z  = blockIdx.y;
    const int tid = threadIdx.x, lane = tid & 31, warp = tid >> 5;
    const int slab = warp >> 1;       // 0..7 : 16-row Q slab
    const int jh   = warp & 1;        // column half of S / k half of PV

    extern __shared__ float sm[];
    unsigned* Qs = (unsigned*)(sm + QS_OFF);
    float* Ksb[2] = { sm + KS_OFF, sm + KS_OFF + 8704 };
    float* Vsb[2] = { sm + VS_OFF, sm + VS_OFF + 9216 };

    const float* Qg = qh + ((long long)z * Sq + qt * 128) * DHq;
    const float* Kg = kh + (long long)z * Sq * DHq;
    const float* Vg = vh + (long long)z * Sq * DHq;

    // Q fill: scaled 1/8, tf32 once
    for (int i = tid; i < 128 * 16; i += 512) {
        int r = i >> 4, c4 = (i & 15) * 4;
        float4 v = *(const float4*)&Qg[r * 64 + c4];
        unsigned* d = &Qs[r * 68 + c4];
        d[0] = f2tf32(v.x * 0.125f); d[1] = f2tf32(v.y * 0.125f);
        d[2] = f2tf32(v.z * 0.125f); d[3] = f2tf32(v.w * 0.125f);
    }

    auto loadK = [&](int kt, int buf) {
        for (int i = tid; i < 128 * 16; i += 512) {
            int r = i >> 4, c4 = (i & 15) * 4;
            cpa16(&Ksb[buf][r * 68 + c4], &Kg[((long long)kt * 128 + r) * 64 + c4]);
        }
    };
    auto loadV = [&](int kt, int buf) {
        for (int i = tid; i < 128 * 16; i += 512) {
            int r = i >> 4, c4 = (i & 15) * 4;
            cpa16(&Vsb[buf][r * 72 + c4], &Vg[((long long)kt * 128 + r) * 64 + c4]);
        }
    };
    auto cvtK = [&](int buf) {
        for (int i = tid; i < 128 * 16; i += 512) {
            int r = i >> 4, c4 = (i & 15) * 4;
            cvt4_inplace(&Ksb[buf][r * 68 + c4]);
        }
    };
    auto cvtV = [&](int buf) {
        for (int i = tid; i < 128 * 16; i += 512) {
            int r = i >> 4, c4 = (i & 15) * 4;
            cvt4_inplace(&Vsb[buf][r * 72 + c4]);
        }
    };

    const unsigned* Qw = &Qs[(slab * 16) * 68];
    const int rq = lane >> 2;
    const int rbase = qt * 128 + slab * 16 + rq;

    float cacc[8][4] = {};
    float l0 = 0.f, l1 = 0.f;
    float p[8][4];

    loadK(0, 0); loadV(0, 0); cp_commit();

    for (int kt = 0; kt <= qt; kt++) {
        int buf = kt & 1;
        __syncthreads();
        if (kt < qt) { loadK(kt + 1, buf ^ 1); loadV(kt + 1, buf ^ 1); }
        cp_commit();
        cp_wait1();
        __syncthreads();
        cvtK(buf); cvtV(buf);
        __syncthreads();

        const unsigned* Kb = (const unsigned*)Ksb[buf];
        const unsigned* Vb = (const unsigned*)Vsb[buf];

        // ---- S = Q @ K^T (warp's 64-column half) ----
#pragma unroll
        for (int j = 0; j < 8; j++) { p[j][0] = p[j][1] = p[j][2] = p[j][3] = 0.f; }
#pragma unroll
        for (int ks = 0; ks < 8; ks++) {
            int kc = ks * 8 + (lane & 3);
            unsigned a0 = Qw[rq * 68 + kc];
            unsigned a1 = Qw[(rq + 8) * 68 + kc];
            unsigned a2 = Qw[rq * 68 + kc + 4];
            unsigned a3 = Qw[(rq + 8) * 68 + kc + 4];
#pragma unroll
            for (int j = 0; j < 8; j++) {
                int n = jh * 64 + j * 8 + rq;
                mma8(p[j], a0, a1, a2, a3, Kb[n * 68 + kc], Kb[n * 68 + kc + 4]);
            }
        }

        // ---- mask + exp + partial row-sum ----
        bool diag = (kt == qt);
#pragma unroll
        for (int j = 0; j < 8; j++) {
            int c0 = kt * 128 + jh * 64 + j * 8 + 2 * (lane & 3);
            float e0 = (!diag || c0     <= rbase    ) ? __expf(p[j][0]) : 0.f;
            float e1 = (!diag || c0 + 1 <= rbase    ) ? __expf(p[j][1]) : 0.f;
            float e2 = (!diag || c0     <= rbase + 8) ? __expf(p[j][2]) : 0.f;
            float e3 = (!diag || c0 + 1 <= rbase + 8) ? __expf(p[j][3]) : 0.f;
            p[j][0] = e0; p[j][1] = e1; p[j][2] = e2; p[j][3] = e3;
            l0 += e0 + e1; l1 += e2 + e3;
        }

        // ---- ctx += P @ V over this warp's k-half ----
        int hlo = (lane & ~3) | ((lane & 3) >> 1);
        int hhi = hlo | 2;
        bool odd = lane & 1;
#pragma unroll
        for (int t = 0; t < 8; t++) {
            float v00 = __shfl_sync(0xffffffffu, p[t][0], hlo);
            float v01 = __shfl_sync(0xffffffffu, p[t][1], hlo);
            float v20 = __shfl_sync(0xffffffffu, p[t][2], hlo);
            float v21 = __shfl_sync(0xffffffffu, p[t][3], hlo);
            float w00 = __shfl_sync(0xffffffffu, p[t][0], hhi);
            float w01 = __shfl_sync(0xffffffffu, p[t][1], hhi);
            float w20 = __shfl_sync(0xffffffffu, p[t][2], hhi);
            float w21 = __shfl_sync(0xffffffffu, p[t][3], hhi);
            unsigned a0 = f2tf32(odd ? v01 : v00);
            unsigned a1 = f2tf32(odd ? v21 : v20);
            unsigned a2 = f2tf32(odd ? w01 : w00);
            unsigned a3 = f2tf32(odd ? w21 : w20);
            int kr = (jh * 8 + t) * 8 + (lane & 3);
#pragma unroll
            for (int j = 0; j < 8; j++) {
                int n = j * 8 + rq;
                mma8(cacc[j], a0, a1, a2, a3, Vb[kr * 72 + n], Vb[(kr + 4) * 72 + n]);
            }
        }
    }

    // ---- quad-reduce partial l ----
    l0 += __shfl_xor_sync(0xffffffffu, l0, 1);
    l0 += __shfl_xor_sync(0xffffffffu, l0, 2);
    l1 += __shfl_xor_sync(0xffffffffu, l1, 1);
    l1 += __shfl_xor_sync(0xffffffffu, l1, 2);

    // ---- merge warp-pair halves via smem staging (reuse K buffer) ----
    float* stg = sm + KS_OFF;   // 8 slabs * 32 lanes * 34 floats = 8704 words
    __syncthreads();
    float* s = stg + slab * (32 * 34) + lane * 34;
    if (jh == 1) {
#pragma unroll
        for (int j = 0; j < 8; j++)
#pragma unroll
            for (int e = 0; e < 4; e++) s[j * 4 + e] = cacc[j][e];
        s[32] = l0; s[33] = l1;
    }
    __syncthreads();
    float inv0 = 0.f, inv1 = 0.f;
    if (jh == 0) {
#pragma unroll
        for (int j = 0; j < 8; j++)
#pragma unroll
            for (int e = 0; e < 4; e++) cacc[j][e] += s[j * 4 + e];
        l0 += s[32]; l1 += s[33];
        inv0 = 1.0f / l0; inv1 = 1.0f / l1;

        int b_ = z >> 4, h_ = z & 15;
        long long base0 = ((long long)b_ * Sq + rbase) * DM + h_ * 64;
        long long base1 = base0 + 8LL * DM;
#pragma unroll
        for (int j = 0; j < 8; j++) {
            int d = j * 8 + 2 * (lane & 3);
            *(float2*)&ctx[base0 + d] = make_float2(cacc[j][0] * inv0, cacc[j][1] * inv0);
            *(float2*)&ctx[base1 + d] = make_float2(cacc[j][2] * inv1, cacc[j][3] * inv1);
        }
        s[32] = inv0; s[33] = inv1;   // broadcast for pass B
    }
    __syncthreads();
    if (jh == 1) { inv0 = s[32]; inv1 = s[33]; }

    // ---- Pass B: write normalized attn ----
    if (write_attn) {
        float* A = attn + (long long)z * Sq * Sq;
        __syncthreads();
        loadK(0, 0); cp_commit();
        for (int kt = 0; kt <= qt; kt++) {
            int buf = kt & 1;
            __syncthreads();
            if (kt < qt) loadK(kt + 1, buf ^ 1);
            cp_commit();
            cp_wait1();
            __syncthreads();
            cvtK(buf);
            __syncthreads();

            const unsigned* Kb = (const unsigned*)Ksb[buf];
#pragma unroll
            for (int j = 0; j < 8; j++) { p[j][0] = p[j][1] = p[j][2] = p[j][3] = 0.f; }
#pragma unroll
            for (int ks = 0; ks < 8; ks++) {
                int kc = ks * 8 + (lane & 3);
                unsigned a0 = Qw[rq * 68 + kc];
                unsigned a1 = Qw[(rq + 8) * 68 + kc];
                unsigned a2 = Qw[rq * 68 + kc + 4];
                unsigned a3 = Qw[(rq + 8) * 68 + kc + 4];
#pragma unroll
                for (int j = 0; j < 8; j++) {
                    int n = jh * 64 + j * 8 + rq;
                    mma8(p[j], a0, a1, a2, a3, Kb[n * 68 + kc], Kb[n * 68 + kc + 4]);
                }
            }
            bool diag = (kt == qt);
            long long row0 = (long long)rbase * Sq;
            long long row1 = (long long)(rbase + 8) * Sq;
#pragma unroll
            for (int j = 0; j < 8; j++) {
                int c0 = kt * 128 + jh * 64 + j * 8 + 2 * (lane & 3);
                float e0 = (!diag || c0     <= rbase    ) ? __expf(p[j][0]) * inv0 : 0.f;
                float e1 = (!diag || c0 + 1 <= rbase    ) ? __expf(p[j][1]) * inv0 : 0.f;
                float e2 = (!diag || c0     <= rbase + 8) ? __expf(p[j][2]) * inv1 : 0.f;
                float e3 = (!diag || c0 + 1 <= rbase + 8) ? __expf(p[j][3]) * inv1 : 0.f;
                *(float2*)&A[row0 + c0] = make_float2(e0, e1);
                *(float2*)&A[row1 + c0] = make_float2(e2, e3);
            }
        }
        // zero-fill the strictly-causal-upper region
        int cEnd = (qt + 1) * 128;
        int nz4 = (Sq - cEnd) >> 2;
        if (nz4 > 0) {
            float4 z4 = make_float4(0.f, 0.f, 0.f, 0.f);
            for (int i = tid; i < 128 * nz4; i += 512) {
                int r = i / nz4, c = (i - r * nz4) * 4;
                *(float4*)&A[(long long)(qt * 128 + r) * Sq + cEnd + c] = z4;
            }
        }
    }
}

// ---------------------------------------------------------------------------
// kernel_launch
// ---------------------------------------------------------------------------
extern "C" void kernel_launch(void* const* d_in, const int* in_sizes, int n_in,
                              void* d_out, int out_size)
{
    const float* q  = (const float*)d_in[0];
    const float* k  = (const float*)d_in[1];
    const float* v  = (const float*)d_in[2];
    // d_in[3] = causal tril mask (handled analytically)
    const float* wq = (const float*)d_in[4];
    const float* bq = (const float*)d_in[5];
    const float* wk = (const float*)d_in[6];
    const float* bk = (const float*)d_in[7];
    const float* wv = (const float*)d_in[8];
    const float* bv = (const float*)d_in[9];
    const float* wo = (const float*)d_in[10];
    const float* bo = (const float*)d_in[11];
    float* out = (float*)d_out;

    float *qh, *kh, *vh, *ctx;
    cudaGetSymbolAddress((void**)&qh,  g_qh);
    cudaGetSymbolAddress((void**)&kh,  g_kh);
    cudaGetSymbolAddress((void**)&vh,  g_vh);
    cudaGetSymbolAddress((void**)&ctx, g_ctx);

    const long long OUT_E  = (long long)Bq * Sq * DM;
    const long long ATTN_E = (long long)Bq * Hq * Sq * Sq;
    int write_attn = ((long long)out_size >= OUT_E + ATTN_E) ? 1 : 0;
    float* attn = out + OUT_E;

    static int attr_done = 0;
    if (!attr_done) {
        cudaFuncSetAttribute(gemm_tc, cudaFuncAttributeMaxDynamicSharedMemorySize, G_SMEM_BYTES);
        cudaFuncSetAttribute(attn_flash, cudaFuncAttributeMaxDynamicSharedMemorySize, F_SMEM_BYTES);
        attr_done = 1;
    }

    // 1: fused QKV projections
    GemmP pq = {};
    pq.X = q;  pq.W = wq; pq.bias = bq; pq.Y = qh;
    pq.X1 = k; pq.W1 = wk; pq.b1 = bk; pq.Y1 = kh;
    pq.X2 = v; pq.W2 = wv; pq.b2 = bv; pq.Y2 = vh;
    pq.M = Bq * Sq; pq.N = DM; pq.K = DM; pq.out_mode = 1; pq.qkv = 1;
    gemm_tc<<<dim3(DM / 128, (Bq * Sq) / 128, 3), 256, G_SMEM_BYTES>>>(pq);

    // 2: fused flash attention (+ attn output)
    attn_flash<<<dim3(Sq / 128, Bq * Hq, 1), 512, F_SMEM_BYTES>>>(
        qh, kh, vh, ctx, attn, write_attn);

    // 3: out = ctx @ wo^T + bo
    GemmP po = {};
    po.X = ctx; po.W = wo; po.bias = bo; po.Y = out;
    po.M = Bq * Sq; po.N = DM; po.K = DM; po.out_mode = 0; po.qkv = 0;
    gemm_tc<<<dim3(DM / 128, (Bq * Sq) / 128, 1), 256, G_SMEM_BYTES>>>(po);
}

// round 7
// speedup vs baseline: 1.1360x; 1.1360x over previous
#include <cuda_runtime.h>
#include <math.h>

// Problem constants
#define Bq 2
#define Sq 2048
#define DM 1024
#define Hq 16
#define DHq 64

// ---------------------------------------------------------------------------
// Scratch (__device__ globals; no runtime allocation)
// qh/kh/vh hold TF32 BIT PATTERNS (written by projection epilogue).
// qh additionally has the 1/8 score scale folded in.
// ---------------------------------------------------------------------------
__device__ unsigned g_qh [(size_t)Bq * Hq * Sq * DHq];   // [B,H,S,DH] tf32 bits (x0.125)
__device__ unsigned g_kh [(size_t)Bq * Hq * Sq * DHq];   // [B,H,S,DH] tf32 bits
__device__ unsigned g_vh [(size_t)Bq * Hq * Sq * DHq];   // [B,H,S,DH] tf32 bits
__device__ float    g_ctx[(size_t)Bq * Sq * DM];          // [B,S,DM] fp32

// ---------------------------------------------------------------------------
// Helpers
// ---------------------------------------------------------------------------
__device__ __forceinline__ unsigned f2tf32(float f) {
    unsigned r; asm("cvt.rna.tf32.f32 %0, %1;" : "=r"(r) : "f"(f)); return r;
}
__device__ __forceinline__ void cpa16(void* dst, const void* src) {
    unsigned d = (unsigned)__cvta_generic_to_shared(dst);
    asm volatile("cp.async.cg.shared.global [%0], [%1], 16;" :: "r"(d), "l"(src));
}
__device__ __forceinline__ void cp_commit() { asm volatile("cp.async.commit_group;"); }
__device__ __forceinline__ void cp_wait1()  { asm volatile("cp.async.wait_group 1;"); }

__device__ __forceinline__ void mma8(float* c, unsigned a0, unsigned a1, unsigned a2,
                                     unsigned a3, unsigned b0, unsigned b1) {
    asm volatile(
        "mma.sync.aligned.m16n8k8.row.col.f32.tf32.tf32.f32 "
        "{%0,%1,%2,%3}, {%4,%5,%6,%7}, {%8,%9}, {%0,%1,%2,%3};"
        : "+f"(c[0]), "+f"(c[1]), "+f"(c[2]), "+f"(c[3])
        : "r"(a0), "r"(a1), "r"(a2), "r"(a3), "r"(b0), "r"(b1));
}

// ---------------------------------------------------------------------------
// Projection GEMM (round-5 proven shape, 128 regs): Y = (X @ W^T + bias)
// tf32out=1: epilogue stores f2tf32(val * pscale) bit patterns.
// out_mode 0: Y[m*N+n] fp32 ; out_mode 1: head layout ((b*H+h)*S+s)*DH+d
// ---------------------------------------------------------------------------
struct GemmP {
    const float *X, *W, *bias; float *Y;
    const float *X1, *W1, *b1; float *Y1;
    const float *X2, *W2, *b2; float *Y2;
    int M, N, K;
    int out_mode;
    int qkv;
    int tf32out;
    float ps0, ps1, ps2;   // per-operand-set post scale
};

#define AS   36
#define A_WORDS 4608     // 128*36
#define G_SMEM_BYTES (4 * A_WORDS * 4)

__global__ __launch_bounds__(256)
void gemm_tc(GemmP p)
{
    const int m0 = blockIdx.y * 128;
    const int n0 = blockIdx.x * 128;
    const int z  = blockIdx.z;
    const int tid = threadIdx.x, lane = tid & 31, warp = tid >> 5;
    const int wm = warp & 1, wn = warp >> 1;

    const float *X = p.X, *W = p.W, *bias = p.bias; float* Y = p.Y;
    float pscale = p.ps0;
    if (p.qkv) {
        if (z == 1) { X = p.X1; W = p.W1; bias = p.b1; Y = p.Y1; pscale = p.ps1; }
        else if (z == 2) { X = p.X2; W = p.W2; bias = p.b2; Y = p.Y2; pscale = p.ps2; }
    }

    extern __shared__ float sm[];
    float* Abuf[2] = { sm,               sm + A_WORDS     };
    float* Bbuf[2] = { sm + 2 * A_WORDS, sm + 3 * A_WORDS };

    auto loadA = [&](float* As_, int k0) {
        int r0 = tid >> 3, c = (tid & 7) * 4;
#pragma unroll
        for (int it = 0; it < 4; it++) {
            int r = r0 + it * 32;
            cpa16(&As_[r * AS + c], &X[(long long)(m0 + r) * p.K + k0 + c]);
        }
    };
    auto loadB = [&](float* Bs_, int k0) {
        int r0 = tid >> 3, c = (tid & 7) * 4;
#pragma unroll
        for (int it = 0; it < 4; it++) {
            int r = r0 + it * 32;
            cpa16(&Bs_[r * AS + c], &W[(long long)(n0 + r) * p.K + k0 + c]);
        }
    };

    float acc[4][4][4] = {};

    loadA(Abuf[0], 0); loadB(Bbuf[0], 0); cp_commit();
    int st = 0;
    for (int k0 = 0; k0 < p.K; k0 += 32) {
        if (k0 + 32 < p.K) { loadA(Abuf[st ^ 1], k0 + 32); loadB(Bbuf[st ^ 1], k0 + 32); }
        cp_commit();
        cp_wait1();
        __syncthreads();

        const float* As_ = Abuf[st];
        const float* Bs_ = Bbuf[st];
#pragma unroll
        for (int kk = 0; kk < 32; kk += 8) {
            unsigned a[4][4];
#pragma unroll
            for (int i = 0; i < 4; i++) {
                int mr = wm * 64 + i * 16 + (lane >> 2);
                int kc = kk + (lane & 3);
                a[i][0] = f2tf32(As_[mr * AS + kc]);
                a[i][1] = f2tf32(As_[(mr + 8) * AS + kc]);
                a[i][2] = f2tf32(As_[mr * AS + kc + 4]);
                a[i][3] = f2tf32(As_[(mr + 8) * AS + kc + 4]);
            }
            unsigned b[4][2];
#pragma unroll
            for (int j = 0; j < 4; j++) {
                int nr = wn * 32 + j * 8 + (lane >> 2);
                int kc = kk + (lane & 3);
                b[j][0] = f2tf32(Bs_[nr * AS + kc]);
                b[j][1] = f2tf32(Bs_[nr * AS + kc + 4]);
            }
#pragma unroll
            for (int i = 0; i < 4; i++)
#pragma unroll
                for (int j = 0; j < 4; j++)
                    mma8(acc[i][j], a[i][0], a[i][1], a[i][2], a[i][3], b[j][0], b[j][1]);
        }
        __syncthreads();
        st ^= 1;
    }

#pragma unroll
    for (int i = 0; i < 4; i++)
#pragma unroll
        for (int j = 0; j < 4; j++)
#pragma unroll
            for (int h = 0; h < 2; h++) {
                int m = m0 + wm * 64 + i * 16 + (lane >> 2) + h * 8;
                int n = n0 + wn * 32 + j * 8 + (lane & 3) * 2;
                float v0 = acc[i][j][h * 2]     + (bias ? bias[n]     : 0.f);
                float v1 = acc[i][j][h * 2 + 1] + (bias ? bias[n + 1] : 0.f);
                long long idx;
                if (p.out_mode == 0) {
                    idx = (long long)m * p.N + n;
                } else {
                    int b_ = m >> 11;
                    int s  = m & (Sq - 1);
                    int hh = n >> 6;
                    int d  = n & (DHq - 1);
                    idx = (((long long)b_ * Hq + hh) * Sq + s) * DHq + d;
                }
                if (p.tf32out) {
                    unsigned u0 = f2tf32(v0 * pscale);
                    unsigned u1 = f2tf32(v1 * pscale);
                    *(uint2*)&Y[idx] = make_uint2(u0, u1);
                } else {
                    *(float2*)&Y[idx] = make_float2(v0, v1);
                }
            }
}

// ---------------------------------------------------------------------------
// Fused flash attention (round-5 shape: 256 threads, 8 warps x 16 rows).
// Q/K/V arrive as PRE-CONVERTED tf32 bits (Q prescaled 1/8) -> zero cvt on
// the Q/K/V paths. P fragments converted once per PV use (64 cvt/tile).
// qt reversed so long causal blocks schedule first.
// ---------------------------------------------------------------------------
#define QS_OFF 0
#define KS_OFF 8704            // Qs: 128*68
#define VS_OFF (8704 + 2*8704) // Ks: 2 x 128*68
#define F_SMEM_WORDS (26112 + 2*9216)
#define F_SMEM_BYTES (F_SMEM_WORDS * 4)

__global__ __launch_bounds__(256, 1)
void attn_flash(const unsigned* __restrict__ qh, const unsigned* __restrict__ kh,
                const unsigned* __restrict__ vh, float* __restrict__ ctx,
                float* __restrict__ attn, int write_attn)
{
    const int qt = (int)gridDim.x - 1 - (int)blockIdx.x;
    const int z  = blockIdx.y;
    const int tid = threadIdx.x, lane = tid & 31, warp = tid >> 5;

    extern __shared__ float sm[];
    unsigned* Qs = (unsigned*)(sm + QS_OFF);
    unsigned* Ksb[2] = { (unsigned*)(sm + KS_OFF), (unsigned*)(sm + KS_OFF) + 8704 };
    unsigned* Vsb[2] = { (unsigned*)(sm + VS_OFF), (unsigned*)(sm + VS_OFF) + 9216 };

    const unsigned* Qg = qh + ((long long)z * Sq + qt * 128) * DHq;
    const unsigned* Kg = kh + (long long)z * Sq * DHq;
    const unsigned* Vg = vh + (long long)z * Sq * DHq;

    // Q fill: raw copy (already tf32 bits, prescaled)
    for (int i = tid; i < 128 * 16; i += 256) {
        int r = i >> 4, c4 = (i & 15) * 4;
        *(uint4*)&Qs[r * 68 + c4] = *(const uint4*)&Qg[r * 64 + c4];
    }

    auto loadK = [&](int kt, int buf) {
        for (int i = tid; i < 128 * 16; i += 256) {
            int r = i >> 4, c4 = (i & 15) * 4;
            cpa16(&Ksb[buf][r * 68 + c4], &Kg[((long long)kt * 128 + r) * 64 + c4]);
        }
    };
    auto loadV = [&](int kt, int buf) {
        for (int i = tid; i < 128 * 16; i += 256) {
            int r = i >> 4, c4 = (i & 15) * 4;
            cpa16(&Vsb[buf][r * 72 + c4], &Vg[((long long)kt * 128 + r) * 64 + c4]);
        }
    };

    const unsigned* Qw = &Qs[(warp * 16) * 68];
    const int rq = lane >> 2;
    const int rbase = qt * 128 + warp * 16 + rq;

    float cacc[8][4] = {};
    float l0 = 0.f, l1 = 0.f;
    float p[16][4];

    loadK(0, 0); loadV(0, 0); cp_commit();

    for (int kt = 0; kt <= qt; kt++) {
        int buf = kt & 1;
        __syncthreads();
        if (kt < qt) { loadK(kt + 1, buf ^ 1); loadV(kt + 1, buf ^ 1); }
        cp_commit();
        cp_wait1();
        __syncthreads();

        const unsigned* Kb = Ksb[buf];
        const unsigned* Vb = Vsb[buf];

        // ---- S = Q @ K^T (raw tf32 frag loads) ----
#pragma unroll
        for (int j = 0; j < 16; j++) { p[j][0] = p[j][1] = p[j][2] = p[j][3] = 0.f; }
#pragma unroll
        for (int ks = 0; ks < 8; ks++) {
            int kc = ks * 8 + (lane & 3);
            unsigned a0 = Qw[rq * 68 + kc];
            unsigned a1 = Qw[(rq + 8) * 68 + kc];
            unsigned a2 = Qw[rq * 68 + kc + 4];
            unsigned a3 = Qw[(rq + 8) * 68 + kc + 4];
#pragma unroll
            for (int j = 0; j < 16; j++) {
                int n = j * 8 + rq;
                mma8(p[j], a0, a1, a2, a3, Kb[n * 68 + kc], Kb[n * 68 + kc + 4]);
            }
        }

        // ---- mask + exp + row-sum ----
        bool diag = (kt == qt);
#pragma unroll
        for (int j = 0; j < 16; j++) {
            int c0 = kt * 128 + j * 8 + 2 * (lane & 3);
            float e0 = (!diag || c0     <= rbase    ) ? __expf(p[j][0]) : 0.f;
            float e1 = (!diag || c0 + 1 <= rbase    ) ? __expf(p[j][1]) : 0.f;
            float e2 = (!diag || c0     <= rbase + 8) ? __expf(p[j][2]) : 0.f;
            float e3 = (!diag || c0 + 1 <= rbase + 8) ? __expf(p[j][3]) : 0.f;
            p[j][0] = e0; p[j][1] = e1; p[j][2] = e2; p[j][3] = e3;
            l0 += e0 + e1; l1 += e2 + e3;
        }

        // ---- ctx += P @ V (A-frags via quad shuffles, V raw tf32) ----
        int hlo = (lane & ~3) | ((lane & 3) >> 1);
        int hhi = hlo | 2;
        bool odd = lane & 1;
#pragma unroll
        for (int t = 0; t < 16; t++) {
            float v00 = __shfl_sync(0xffffffffu, p[t][0], hlo);
            float v01 = __shfl_sync(0xffffffffu, p[t][1], hlo);
            float v20 = __shfl_sync(0xffffffffu, p[t][2], hlo);
            float v21 = __shfl_sync(0xffffffffu, p[t][3], hlo);
            float w00 = __shfl_sync(0xffffffffu, p[t][0], hhi);
            float w01 = __shfl_sync(0xffffffffu, p[t][1], hhi);
            float w20 = __shfl_sync(0xffffffffu, p[t][2], hhi);
            float w21 = __shfl_sync(0xffffffffu, p[t][3], hhi);
            unsigned a0 = f2tf32(odd ? v01 : v00);
            unsigned a1 = f2tf32(odd ? v21 : v20);
            unsigned a2 = f2tf32(odd ? w01 : w00);
            unsigned a3 = f2tf32(odd ? w21 : w20);
            int kr = t * 8 + (lane & 3);
#pragma unroll
            for (int j = 0; j < 8; j++) {
                int n = j * 8 + rq;
                mma8(cacc[j], a0, a1, a2, a3, Vb[kr * 72 + n], Vb[(kr + 4) * 72 + n]);
            }
        }
    }

    // ---- finalize l ----
    l0 += __shfl_xor_sync(0xffffffffu, l0, 1);
    l0 += __shfl_xor_sync(0xffffffffu, l0, 2);
    l1 += __shfl_xor_sync(0xffffffffu, l1, 1);
    l1 += __shfl_xor_sync(0xffffffffu, l1, 2);
    float inv0 = 1.0f / l0, inv1 = 1.0f / l1;

    // ---- ctx epilogue -> g_ctx [b][s][h*64+d] (fp32) ----
    {
        int b_ = z >> 4, h_ = z & 15;
        long long base0 = ((long long)b_ * Sq + rbase) * DM + h_ * 64;
        long long base1 = base0 + 8LL * DM;
#pragma unroll
        for (int j = 0; j < 8; j++) {
            int d = j * 8 + 2 * (lane & 3);
            *(float2*)&ctx[base0 + d] = make_float2(cacc[j][0] * inv0, cacc[j][1] * inv0);
            *(float2*)&ctx[base1 + d] = make_float2(cacc[j][2] * inv1, cacc[j][3] * inv1);
        }
    }

    // ---- Pass B: write normalized attn ----
    if (write_attn) {
        float* A = attn + (long long)z * Sq * Sq;
        __syncthreads();
        loadK(0, 0); cp_commit();
        for (int kt = 0; kt <= qt; kt++) {
            int buf = kt & 1;
            __syncthreads();
            if (kt < qt) loadK(kt + 1, buf ^ 1);
            cp_commit();
            cp_wait1();
            __syncthreads();

            const unsigned* Kb = Ksb[buf];
#pragma unroll
            for (int j = 0; j < 16; j++) { p[j][0] = p[j][1] = p[j][2] = p[j][3] = 0.f; }
#pragma unroll
            for (int ks = 0; ks < 8; ks++) {
                int kc = ks * 8 + (lane & 3);
                unsigned a0 = Qw[rq * 68 + kc];
                unsigned a1 = Qw[(rq + 8) * 68 + kc];
                unsigned a2 = Qw[rq * 68 + kc + 4];
                unsigned a3 = Qw[(rq + 8) * 68 + kc + 4];
#pragma unroll
                for (int j = 0; j < 16; j++) {
                    int n = j * 8 + rq;
                    mma8(p[j], a0, a1, a2, a3, Kb[n * 68 + kc], Kb[n * 68 + kc + 4]);
                }
            }
            bool diag = (kt == qt);
            long long row0 = (long long)rbase * Sq;
            long long row1 = (long long)(rbase + 8) * Sq;
#pragma unroll
            for (int j = 0; j < 16; j++) {
                int c0 = kt * 128 + j * 8 + 2 * (lane & 3);
                float e0 = (!diag || c0     <= rbase    ) ? __expf(p[j][0]) * inv0 : 0.f;
                float e1 = (!diag || c0 + 1 <= rbase    ) ? __expf(p[j][1]) * inv0 : 0.f;
                float e2 = (!diag || c0     <= rbase + 8) ? __expf(p[j][2]) * inv1 : 0.f;
                float e3 = (!diag || c0 + 1 <= rbase + 8) ? __expf(p[j][3]) * inv1 : 0.f;
                *(float2*)&A[row0 + c0] = make_float2(e0, e1);
                *(float2*)&A[row1 + c0] = make_float2(e2, e3);
            }
        }
        int cEnd = (qt + 1) * 128;
        int nz4 = (Sq - cEnd) >> 2;
        if (nz4 > 0) {
            float4 z4 = make_float4(0.f, 0.f, 0.f, 0.f);
            for (int i = tid; i < 128 * nz4; i += 256) {
                int r = i / nz4, c = (i - r * nz4) * 4;
                *(float4*)&A[(long long)(qt * 128 + r) * Sq + cEnd + c] = z4;
            }
        }
    }
}

// ---------------------------------------------------------------------------
// kernel_launch
// ---------------------------------------------------------------------------
extern "C" void kernel_launch(void* const* d_in, const int* in_sizes, int n_in,
                              void* d_out, int out_size)
{
    const float* q  = (const float*)d_in[0];
    const float* k  = (const float*)d_in[1];
    const float* v  = (const float*)d_in[2];
    // d_in[3] = causal tril mask (handled analytically)
    const float* wq = (const float*)d_in[4];
    const float* bq = (const float*)d_in[5];
    const float* wk = (const float*)d_in[6];
    const float* bk = (const float*)d_in[7];
    const float* wv = (const float*)d_in[8];
    const float* bv = (const float*)d_in[9];
    const float* wo = (const float*)d_in[10];
    const float* bo = (const float*)d_in[11];
    float* out = (float*)d_out;

    unsigned *qh, *kh, *vh; float *ctx;
    cudaGetSymbolAddress((void**)&qh,  g_qh);
    cudaGetSymbolAddress((void**)&kh,  g_kh);
    cudaGetSymbolAddress((void**)&vh,  g_vh);
    cudaGetSymbolAddress((void**)&ctx, g_ctx);

    const long long OUT_E  = (long long)Bq * Sq * DM;
    const long long ATTN_E = (long long)Bq * Hq * Sq * Sq;
    int write_attn = ((long long)out_size >= OUT_E + ATTN_E) ? 1 : 0;
    float* attn = out + OUT_E;

    static int attr_done = 0;
    if (!attr_done) {
        cudaFuncSetAttribute(gemm_tc, cudaFuncAttributeMaxDynamicSharedMemorySize, G_SMEM_BYTES);
        cudaFuncSetAttribute(attn_flash, cudaFuncAttributeMaxDynamicSharedMemorySize, F_SMEM_BYTES);
        attr_done = 1;
    }

    // 1: fused QKV projections -> tf32-bit head layouts (Q folds 1/8)
    GemmP pq = {};
    pq.X = q;  pq.W = wq; pq.bias = bq; pq.Y = (float*)qh;
    pq.X1 = k; pq.W1 = wk; pq.b1 = bk; pq.Y1 = (float*)kh;
    pq.X2 = v; pq.W2 = wv; pq.b2 = bv; pq.Y2 = (float*)vh;
    pq.M = Bq * Sq; pq.N = DM; pq.K = DM; pq.out_mode = 1; pq.qkv = 1;
    pq.tf32out = 1; pq.ps0 = 0.125f; pq.ps1 = 1.f; pq.ps2 = 1.f;
    gemm_tc<<<dim3(DM / 128, (Bq * Sq) / 128, 3), 256, G_SMEM_BYTES>>>(pq);

    // 2: fused flash attention (+ attn output)
    attn_flash<<<dim3(Sq / 128, Bq * Hq, 1), 256, F_SMEM_BYTES>>>(
        qh, kh, vh, ctx, attn, write_attn);

    // 3: out = ctx @ wo^T + bo  (fp32 output)
    GemmP po = {};
    po.X = ctx; po.W = wo; po.bias = bo; po.Y = out;
    po.M = Bq * Sq; po.N = DM; po.K = DM; po.out_mode = 0; po.qkv = 0;
    po.tf32out = 0; po.ps0 = 1.f;
    gemm_tc<<<dim3(DM / 128, (Bq * Sq) / 128, 1), 256, G_SMEM_BYTES>>>(po);
}

// round 8
// speedup vs baseline: 1.2510x; 1.1012x over previous
#include <cuda_runtime.h>
#include <math.h>

// Problem constants
#define Bq 2
#define Sq 2048
#define DM 1024
#define Hq 16
#define DHq 64

// ---------------------------------------------------------------------------
// Scratch (__device__ globals; no runtime allocation)
// qh/kh/vh/ctx hold TF32 BIT PATTERNS (written by producer epilogues).
// qh additionally has the 1/8 score scale folded in.
// ---------------------------------------------------------------------------
__device__ unsigned g_qh [(size_t)Bq * Hq * Sq * DHq];   // [B,H,S,DH] tf32 bits (x0.125)
__device__ unsigned g_kh [(size_t)Bq * Hq * Sq * DHq];   // [B,H,S,DH] tf32 bits
__device__ unsigned g_vh [(size_t)Bq * Hq * Sq * DHq];   // [B,H,S,DH] tf32 bits
__device__ unsigned g_ctx[(size_t)Bq * Sq * DM];          // [B,S,DM]   tf32 bits

// ---------------------------------------------------------------------------
// Helpers
// ---------------------------------------------------------------------------
__device__ __forceinline__ unsigned f2tf32(float f) {
    unsigned r; asm("cvt.rna.tf32.f32 %0, %1;" : "=r"(r) : "f"(f)); return r;
}
__device__ __forceinline__ void cpa16(void* dst, const void* src) {
    unsigned d = (unsigned)__cvta_generic_to_shared(dst);
    asm volatile("cp.async.cg.shared.global [%0], [%1], 16;" :: "r"(d), "l"(src));
}
__device__ __forceinline__ void cp_commit() { asm volatile("cp.async.commit_group;"); }
__device__ __forceinline__ void cp_wait1()  { asm volatile("cp.async.wait_group 1;"); }

__device__ __forceinline__ void mma8(float* c, unsigned a0, unsigned a1, unsigned a2,
                                     unsigned a3, unsigned b0, unsigned b1) {
    asm volatile(
        "mma.sync.aligned.m16n8k8.row.col.f32.tf32.tf32.f32 "
        "{%0,%1,%2,%3}, {%4,%5,%6,%7}, {%8,%9}, {%0,%1,%2,%3};"
        : "+f"(c[0]), "+f"(c[1]), "+f"(c[2]), "+f"(c[3])
        : "r"(a0), "r"(a1), "r"(a2), "r"(a3), "r"(b0), "r"(b1));
}

// ---------------------------------------------------------------------------
// Projection GEMM, templated (no runtime epilogue branches):
//   A_TF32:  X elements are pre-converted tf32 bit patterns (raw LDS, no cvt)
//   OUT_TF32: store f2tf32(val * pscale) bit patterns; else fp32
// out_mode 0: Y[m*N+n] ; out_mode 1: head layout ((b*H+h)*S+s)*DH+d
// __launch_bounds__(256, 2): hard 128-reg cap -> 2 CTAs/SM (the perf cliff).
// ---------------------------------------------------------------------------
struct GemmP {
    const float *X, *W, *bias; void *Y;
    const float *X1, *W1, *b1; void *Y1;
    const float *X2, *W2, *b2; void *Y2;
    int M, N, K;
    int out_mode;
    int qkv;
    float ps0, ps1, ps2;
};

#define AS   36
#define A_WORDS 4608     // 128*36
#define G_SMEM_BYTES (4 * A_WORDS * 4)

template <bool A_TF32, bool OUT_TF32>
__global__ __launch_bounds__(256, 2)
void gemm_tc(GemmP p)
{
    const int m0 = blockIdx.y * 128;
    const int n0 = blockIdx.x * 128;
    const int z  = blockIdx.z;
    const int tid = threadIdx.x, lane = tid & 31, warp = tid >> 5;
    const int wm = warp & 1, wn = warp >> 1;

    const float *X = p.X, *W = p.W, *bias = p.bias; void* Y = p.Y;
    float pscale = p.ps0;
    if (p.qkv) {
        if (z == 1) { X = p.X1; W = p.W1; bias = p.b1; Y = p.Y1; pscale = p.ps1; }
        else if (z == 2) { X = p.X2; W = p.W2; bias = p.b2; Y = p.Y2; pscale = p.ps2; }
    }

    extern __shared__ float sm[];
    float* Abuf[2] = { sm,               sm + A_WORDS     };
    float* Bbuf[2] = { sm + 2 * A_WORDS, sm + 3 * A_WORDS };

    auto loadA = [&](float* As_, int k0) {
        int r0 = tid >> 3, c = (tid & 7) * 4;
#pragma unroll
        for (int it = 0; it < 4; it++) {
            int r = r0 + it * 32;
            cpa16(&As_[r * AS + c], &X[(long long)(m0 + r) * p.K + k0 + c]);
        }
    };
    auto loadB = [&](float* Bs_, int k0) {
        int r0 = tid >> 3, c = (tid & 7) * 4;
#pragma unroll
        for (int it = 0; it < 4; it++) {
            int r = r0 + it * 32;
            cpa16(&Bs_[r * AS + c], &W[(long long)(n0 + r) * p.K + k0 + c]);
        }
    };

    float acc[4][4][4] = {};

    loadA(Abuf[0], 0); loadB(Bbuf[0], 0); cp_commit();
    int st = 0;
    for (int k0 = 0; k0 < p.K; k0 += 32) {
        if (k0 + 32 < p.K) { loadA(Abuf[st ^ 1], k0 + 32); loadB(Bbuf[st ^ 1], k0 + 32); }
        cp_commit();
        cp_wait1();
        __syncthreads();

        const float* As_ = Abuf[st];
        const float* Bs_ = Bbuf[st];
        const unsigned* Au = (const unsigned*)As_;
#pragma unroll
        for (int kk = 0; kk < 32; kk += 8) {
            unsigned a[4][4];
#pragma unroll
            for (int i = 0; i < 4; i++) {
                int mr = wm * 64 + i * 16 + (lane >> 2);
                int kc = kk + (lane & 3);
                if (A_TF32) {
                    a[i][0] = Au[mr * AS + kc];
                    a[i][1] = Au[(mr + 8) * AS + kc];
                    a[i][2] = Au[mr * AS + kc + 4];
                    a[i][3] = Au[(mr + 8) * AS + kc + 4];
                } else {
                    a[i][0] = f2tf32(As_[mr * AS + kc]);
                    a[i][1] = f2tf32(As_[(mr + 8) * AS + kc]);
                    a[i][2] = f2tf32(As_[mr * AS + kc + 4]);
                    a[i][3] = f2tf32(As_[(mr + 8) * AS + kc + 4]);
                }
            }
            unsigned b[4][2];
#pragma unroll
            for (int j = 0; j < 4; j++) {
                int nr = wn * 32 + j * 8 + (lane >> 2);
                int kc = kk + (lane & 3);
                b[j][0] = f2tf32(Bs_[nr * AS + kc]);
                b[j][1] = f2tf32(Bs_[nr * AS + kc + 4]);
            }
#pragma unroll
            for (int i = 0; i < 4; i++)
#pragma unroll
                for (int j = 0; j < 4; j++)
                    mma8(acc[i][j], a[i][0], a[i][1], a[i][2], a[i][3], b[j][0], b[j][1]);
        }
        __syncthreads();
        st ^= 1;
    }

#pragma unroll
    for (int i = 0; i < 4; i++)
#pragma unroll
        for (int j = 0; j < 4; j++)
#pragma unroll
            for (int h = 0; h < 2; h++) {
                int m = m0 + wm * 64 + i * 16 + (lane >> 2) + h * 8;
                int n = n0 + wn * 32 + j * 8 + (lane & 3) * 2;
                float v0 = acc[i][j][h * 2]     + (bias ? bias[n]     : 0.f);
                float v1 = acc[i][j][h * 2 + 1] + (bias ? bias[n + 1] : 0.f);
                long long idx;
                if (p.out_mode == 0) {
                    idx = (long long)m * p.N + n;
                } else {
                    int b_ = m >> 11;
                    int s  = m & (Sq - 1);
                    int hh = n >> 6;
                    int d  = n & (DHq - 1);
                    idx = (((long long)b_ * Hq + hh) * Sq + s) * DHq + d;
                }
                if (OUT_TF32) {
                    unsigned u0 = f2tf32(v0 * pscale);
                    unsigned u1 = f2tf32(v1 * pscale);
                    *(uint2*)((unsigned*)Y + idx) = make_uint2(u0, u1);
                } else {
                    *(float2*)((float*)Y + idx) = make_float2(v0, v1);
                }
            }
}

// ---------------------------------------------------------------------------
// Fused flash attention (round-7 version: 256 threads, 8 warps x 16 rows,
// Q/K/V pre-converted tf32 bits, Q prescaled 1/8, qt reversed).
// ---------------------------------------------------------------------------
#define QS_OFF 0
#define KS_OFF 8704            // Qs: 128*68
#define VS_OFF (8704 + 2*8704) // Ks: 2 x 128*68
#define F_SMEM_WORDS (26112 + 2*9216)
#define F_SMEM_BYTES (F_SMEM_WORDS * 4)

__global__ __launch_bounds__(256, 1)
void attn_flash(const unsigned* __restrict__ qh, const unsigned* __restrict__ kh,
                const unsigned* __restrict__ vh, unsigned* __restrict__ ctx,
                float* __restrict__ attn, int write_attn)
{
    const int qt = (int)gridDim.x - 1 - (int)blockIdx.x;
    const int z  = blockIdx.y;
    const int tid = threadIdx.x, lane = tid & 31, warp = tid >> 5;

    extern __shared__ float sm[];
    unsigned* Qs = (unsigned*)(sm + QS_OFF);
    unsigned* Ksb[2] = { (unsigned*)(sm + KS_OFF), (unsigned*)(sm + KS_OFF) + 8704 };
    unsigned* Vsb[2] = { (unsigned*)(sm + VS_OFF), (unsigned*)(sm + VS_OFF) + 9216 };

    const unsigned* Qg = qh + ((long long)z * Sq + qt * 128) * DHq;
    const unsigned* Kg = kh + (long long)z * Sq * DHq;
    const unsigned* Vg = vh + (long long)z * Sq * DHq;

    for (int i = tid; i < 128 * 16; i += 256) {
        int r = i >> 4, c4 = (i & 15) * 4;
        *(uint4*)&Qs[r * 68 + c4] = *(const uint4*)&Qg[r * 64 + c4];
    }

    auto loadK = [&](int kt, int buf) {
        for (int i = tid; i < 128 * 16; i += 256) {
            int r = i >> 4, c4 = (i & 15) * 4;
            cpa16(&Ksb[buf][r * 68 + c4], &Kg[((long long)kt * 128 + r) * 64 + c4]);
        }
    };
    auto loadV = [&](int kt, int buf) {
        for (int i = tid; i < 128 * 16; i += 256) {
            int r = i >> 4, c4 = (i & 15) * 4;
            cpa16(&Vsb[buf][r * 72 + c4], &Vg[((long long)kt * 128 + r) * 64 + c4]);
        }
    };

    const unsigned* Qw = &Qs[(warp * 16) * 68];
    const int rq = lane >> 2;
    const int rbase = qt * 128 + warp * 16 + rq;

    float cacc[8][4] = {};
    float l0 = 0.f, l1 = 0.f;
    float p[16][4];

    loadK(0, 0); loadV(0, 0); cp_commit();

    for (int kt = 0; kt <= qt; kt++) {
        int buf = kt & 1;
        __syncthreads();
        if (kt < qt) { loadK(kt + 1, buf ^ 1); loadV(kt + 1, buf ^ 1); }
        cp_commit();
        cp_wait1();
        __syncthreads();

        const unsigned* Kb = Ksb[buf];
        const unsigned* Vb = Vsb[buf];

#pragma unroll
        for (int j = 0; j < 16; j++) { p[j][0] = p[j][1] = p[j][2] = p[j][3] = 0.f; }
#pragma unroll
        for (int ks = 0; ks < 8; ks++) {
            int kc = ks * 8 + (lane & 3);
            unsigned a0 = Qw[rq * 68 + kc];
            unsigned a1 = Qw[(rq + 8) * 68 + kc];
            unsigned a2 = Qw[rq * 68 + kc + 4];
            unsigned a3 = Qw[(rq + 8) * 68 + kc + 4];
#pragma unroll
            for (int j = 0; j < 16; j++) {
                int n = j * 8 + rq;
                mma8(p[j], a0, a1, a2, a3, Kb[n * 68 + kc], Kb[n * 68 + kc + 4]);
            }
        }

        bool diag = (kt == qt);
#pragma unroll
        for (int j = 0; j < 16; j++) {
            int c0 = kt * 128 + j * 8 + 2 * (lane & 3);
            float e0 = (!diag || c0     <= rbase    ) ? __expf(p[j][0]) : 0.f;
            float e1 = (!diag || c0 + 1 <= rbase    ) ? __expf(p[j][1]) : 0.f;
            float e2 = (!diag || c0     <= rbase + 8) ? __expf(p[j][2]) : 0.f;
            float e3 = (!diag || c0 + 1 <= rbase + 8) ? __expf(p[j][3]) : 0.f;
            p[j][0] = e0; p[j][1] = e1; p[j][2] = e2; p[j][3] = e3;
            l0 += e0 + e1; l1 += e2 + e3;
        }

        int hlo = (lane & ~3) | ((lane & 3) >> 1);
        int hhi = hlo | 2;
        bool odd = lane & 1;
#pragma unroll
        for (int t = 0; t < 16; t++) {
            float v00 = __shfl_sync(0xffffffffu, p[t][0], hlo);
            float v01 = __shfl_sync(0xffffffffu, p[t][1], hlo);
            float v20 = __shfl_sync(0xffffffffu, p[t][2], hlo);
            float v21 = __shfl_sync(0xffffffffu, p[t][3], hlo);
            float w00 = __shfl_sync(0xffffffffu, p[t][0], hhi);
            float w01 = __shfl_sync(0xffffffffu, p[t][1], hhi);
            float w20 = __shfl_sync(0xffffffffu, p[t][2], hhi);
            float w21 = __shfl_sync(0xffffffffu, p[t][3], hhi);
            unsigned a0 = f2tf32(odd ? v01 : v00);
            unsigned a1 = f2tf32(odd ? v21 : v20);
            unsigned a2 = f2tf32(odd ? w01 : w00);
            unsigned a3 = f2tf32(odd ? w21 : w00 == w00 ? w20 : w20);
            a3 = f2tf32(odd ? w21 : w20);
            int kr = t * 8 + (lane & 3);
#pragma unroll
            for (int j = 0; j < 8; j++) {
                int n = j * 8 + rq;
                mma8(cacc[j], a0, a1, a2, a3, Vb[kr * 72 + n], Vb[(kr + 4) * 72 + n]);
            }
        }
    }

    l0 += __shfl_xor_sync(0xffffffffu, l0, 1);
    l0 += __shfl_xor_sync(0xffffffffu, l0, 2);
    l1 += __shfl_xor_sync(0xffffffffu, l1, 1);
    l1 += __shfl_xor_sync(0xffffffffu, l1, 2);
    float inv0 = 1.0f / l0, inv1 = 1.0f / l1;

    // ctx epilogue -> tf32 bit patterns (bit-identical to out-proj's own cvt)
    {
        int b_ = z >> 4, h_ = z & 15;
        long long base0 = ((long long)b_ * Sq + rbase) * DM + h_ * 64;
        long long base1 = base0 + 8LL * DM;
#pragma unroll
        for (int j = 0; j < 8; j++) {
            int d = j * 8 + 2 * (lane & 3);
            *(uint2*)&ctx[base0 + d] =
                make_uint2(f2tf32(cacc[j][0] * inv0), f2tf32(cacc[j][1] * inv0));
            *(uint2*)&ctx[base1 + d] =
                make_uint2(f2tf32(cacc[j][2] * inv1), f2tf32(cacc[j][3] * inv1));
        }
    }

    if (write_attn) {
        float* A = attn + (long long)z * Sq * Sq;
        __syncthreads();
        loadK(0, 0); cp_commit();
        for (int kt = 0; kt <= qt; kt++) {
            int buf = kt & 1;
            __syncthreads();
            if (kt < qt) loadK(kt + 1, buf ^ 1);
            cp_commit();
            cp_wait1();
            __syncthreads();

            const unsigned* Kb = Ksb[buf];
#pragma unroll
            for (int j = 0; j < 16; j++) { p[j][0] = p[j][1] = p[j][2] = p[j][3] = 0.f; }
#pragma unroll
            for (int ks = 0; ks < 8; ks++) {
                int kc = ks * 8 + (lane & 3);
                unsigned a0 = Qw[rq * 68 + kc];
                unsigned a1 = Qw[(rq + 8) * 68 + kc];
                unsigned a2 = Qw[rq * 68 + kc + 4];
                unsigned a3 = Qw[(rq + 8) * 68 + kc + 4];
#pragma unroll
                for (int j = 0; j < 16; j++) {
                    int n = j * 8 + rq;
                    mma8(p[j], a0, a1, a2, a3, Kb[n * 68 + kc], Kb[n * 68 + kc + 4]);
                }
            }
            bool diag = (kt == qt);
            long long row0 = (long long)rbase * Sq;
            long long row1 = (long long)(rbase + 8) * Sq;
#pragma unroll
            for (int j = 0; j < 16; j++) {
                int c0 = kt * 128 + j * 8 + 2 * (lane & 3);
                float e0 = (!diag || c0     <= rbase    ) ? __expf(p[j][0]) * inv0 : 0.f;
                float e1 = (!diag || c0 + 1 <= rbase    ) ? __expf(p[j][1]) * inv0 : 0.f;
                float e2 = (!diag || c0     <= rbase + 8) ? __expf(p[j][2]) * inv1 : 0.f;
                float e3 = (!diag || c0 + 1 <= rbase + 8) ? __expf(p[j][3]) * inv1 : 0.f;
                *(float2*)&A[row0 + c0] = make_float2(e0, e1);
                *(float2*)&A[row1 + c0] = make_float2(e2, e3);
            }
        }
        int cEnd = (qt + 1) * 128;
        int nz4 = (Sq - cEnd) >> 2;
        if (nz4 > 0) {
            float4 z4 = make_float4(0.f, 0.f, 0.f, 0.f);
            for (int i = tid; i < 128 * nz4; i += 256) {
                int r = i / nz4, c = (i - r * nz4) * 4;
                *(float4*)&A[(long long)(qt * 128 + r) * Sq + cEnd + c] = z4;
            }
        }
    }
}

// ---------------------------------------------------------------------------
// kernel_launch
// ---------------------------------------------------------------------------
extern "C" void kernel_launch(void* const* d_in, const int* in_sizes, int n_in,
                              void* d_out, int out_size)
{
    const float* q  = (const float*)d_in[0];
    const float* k  = (const float*)d_in[1];
    const float* v  = (const float*)d_in[2];
    // d_in[3] = causal tril mask (handled analytically)
    const float* wq = (const float*)d_in[4];
    const float* bq = (const float*)d_in[5];
    const float* wk = (const float*)d_in[6];
    const float* bk = (const float*)d_in[7];
    const float* wv = (const float*)d_in[8];
    const float* bv = (const float*)d_in[9];
    const float* wo = (const float*)d_in[10];
    const float* bo = (const float*)d_in[11];
    float* out = (float*)d_out;

    unsigned *qh, *kh, *vh, *ctx;
    cudaGetSymbolAddress((void**)&qh,  g_qh);
    cudaGetSymbolAddress((void**)&kh,  g_kh);
    cudaGetSymbolAddress((void**)&vh,  g_vh);
    cudaGetSymbolAddress((void**)&ctx, g_ctx);

    const long long OUT_E  = (long long)Bq * Sq * DM;
    const long long ATTN_E = (long long)Bq * Hq * Sq * Sq;
    int write_attn = ((long long)out_size >= OUT_E + ATTN_E) ? 1 : 0;
    float* attn = out + OUT_E;

    static int attr_done = 0;
    if (!attr_done) {
        cudaFuncSetAttribute(gemm_tc<false, true>,
                             cudaFuncAttributeMaxDynamicSharedMemorySize, G_SMEM_BYTES);
        cudaFuncSetAttribute(gemm_tc<true, false>,
                             cudaFuncAttributeMaxDynamicSharedMemorySize, G_SMEM_BYTES);
        cudaFuncSetAttribute(attn_flash,
                             cudaFuncAttributeMaxDynamicSharedMemorySize, F_SMEM_BYTES);
        attr_done = 1;
    }

    // 1: fused QKV projections -> tf32-bit head layouts (Q folds 1/8)
    GemmP pq = {};
    pq.X = q;  pq.W = wq; pq.bias = bq; pq.Y = qh;
    pq.X1 = k; pq.W1 = wk; pq.b1 = bk; pq.Y1 = kh;
    pq.X2 = v; pq.W2 = wv; pq.b2 = bv; pq.Y2 = vh;
    pq.M = Bq * Sq; pq.N = DM; pq.K = DM; pq.out_mode = 1; pq.qkv = 1;
    pq.ps0 = 0.125f; pq.ps1 = 1.f; pq.ps2 = 1.f;
    gemm_tc<false, true><<<dim3(DM / 128, (Bq * Sq) / 128, 3), 256, G_SMEM_BYTES>>>(pq);

    // 2: fused flash attention (+ attn output); ctx out as tf32 bits
    attn_flash<<<dim3(Sq / 128, Bq * Hq, 1), 256, F_SMEM_BYTES>>>(
        qh, kh, vh, ctx, attn, write_attn);

    // 3: out = ctx @ wo^T + bo  (ctx pre-converted -> raw LDS A-path)
    GemmP po = {};
    po.X = (const float*)ctx; po.W = wo; po.bias = bo; po.Y = out;
    po.M = Bq * Sq; po.N = DM; po.K = DM; po.out_mode = 0; po.qkv = 0;
    po.ps0 = 1.f;
    gemm_tc<true, false><<<dim3(DM / 128, (Bq * Sq) / 128, 1), 256, G_SMEM_BYTES>>>(po);
}